// round 14
// baseline (speedup 1.0000x reference)
#include <cuda_runtime.h>
#include <cuda_fp16.h>
#include <math.h>
#include <stdint.h>

// ---------------------------------------------------------------------------
// InteractionNetwork, HMMA (mma.sync m16n8k16 f16), base-sm_100 target.
// R14 = R13 (__ldg frag table, no block barrier, 45KB smem) with
// __launch_bounds__(256, 4): pins regs to <=64 (proven feasible in R12) so
// 4 blocks/SM actually materialize -> occupancy 23% -> ~50%.
// Math identical: AhiBh + AloBh + AhiBl via composite B tables.
// ---------------------------------------------------------------------------

constexpr int N_MAX = 100000;
constexpr int E_MAX = 2000000;

__device__ float4 g_emsg[E_MAX];
__device__ float  g_aggr[N_MAX * 4];
__device__ float4 g_x4 [N_MAX];    // padded copy of x
__device__ float4 g_xt4[N_MAX];    // padded x_tilde

// --- constant bank ----------------------------------------------------------
constexpr int R1W1T = 0;
constexpr int R1B1  = 400;
constexpr int R1W2T = 440;
constexpr int R1B2  = 2040;
constexpr int R1W3T = 2080;   // [40][4]
constexpr int R1B3  = 2240;
constexpr int OW1T  = 2244;
constexpr int OB1   = 2524;
constexpr int OW2T  = 2564;
constexpr int OB2   = 4164;
constexpr int OW3T  = 4204;
constexpr int OB3   = 4364;
constexpr int R2W1T = 4368;
constexpr int R2B1  = 4768;
constexpr int R2W2T = 4808;
constexpr int R2B2  = 6408;
constexpr int R2W3  = 6448;
constexpr int R2B3  = 6488;
constexpr int CP_TOTAL = 6496;

__constant__ float cP[CP_TOTAL];
__device__   float g_cparams[CP_TOTAL];

// B fragments: [kernel(2)][f(10)][nt(5)][lane(32)] uint2 {b0,b1}
constexpr int FRAG_CNT = 10 * 5 * 32;        // 1600 uint2 per kernel
__device__ uint2 g_bfrag[2 * FRAG_CNT];

// --- helpers ----------------------------------------------------------------
__device__ __forceinline__ uint32_t smem_to_u32(const void* p) {
    uint32_t a;
    asm("{ .reg .u64 t; cvta.to.shared.u64 t, %1; cvt.u32.u64 %0, t; }"
        : "=r"(a) : "l"(p));
    return a;
}

__device__ __forceinline__ uint32_t h2pack(float a, float b) {
    __half2 h;
    h.x = __float2half_rn(a);
    h.y = __float2half_rn(b);
    return *reinterpret_cast<uint32_t*>(&h);
}

__device__ __forceinline__ void split2h(float v0, float v1,
                                        uint32_t& hi, uint32_t& lo) {
    const __half h0 = __float2half_rn(v0);
    const __half h1 = __float2half_rn(v1);
    __half2 H; H.x = h0; H.y = h1;
    __half2 L;
    L.x = __float2half_rn(v0 - __half2float(h0));
    L.y = __float2half_rn(v1 - __half2float(h1));
    hi = *reinterpret_cast<uint32_t*>(&H);
    lo = *reinterpret_cast<uint32_t*>(&L);
}

__device__ __forceinline__ void ldsm4(uint32_t* r, uint32_t addr) {
    asm volatile("ldmatrix.sync.aligned.m8n8.x4.shared.b16 {%0,%1,%2,%3}, [%4];"
                 : "=r"(r[0]), "=r"(r[1]), "=r"(r[2]), "=r"(r[3]) : "r"(addr));
}

__device__ __forceinline__ void mma16816(float* c, const uint32_t* a,
                                         uint32_t b0, uint32_t b1) {
    asm volatile("mma.sync.aligned.m16n8k16.row.col.f32.f16.f16.f32 "
                 "{%0,%1,%2,%3}, {%4,%5,%6,%7}, {%8,%9}, {%0,%1,%2,%3};"
                 : "+f"(c[0]), "+f"(c[1]), "+f"(c[2]), "+f"(c[3])
                 : "r"(a[0]), "r"(a[1]), "r"(a[2]), "r"(a[3]), "r"(b0), "r"(b1));
}

// smem: single A plane [8 warps][32 rows][176B]  (no frag table in smem)
constexpr int ROWB = 176;                    // 16B-aligned; conflict-free ldmatrix
constexpr int WARP_PLANE = 32 * ROWB;        // 5632
constexpr int SMEM_TOTAL = 8 * WARP_PLANE;   // 45056 -> 4 blocks/SM at <=64 regs

__device__ __forceinline__ uint32_t a_addr(uint32_t base, int mt, int kt, int lane) {
    const int g = lane >> 3;
    const int row = mt * 16 + (lane & 7) + ((g & 1) << 3);
    const int col = ((g >> 1) << 4) + kt * 32;
    return base + row * ROWB + col;
}

// ---------------------------------------------------------------------------
// KSEL: 0 = R1 (edge_msg), 1 = R2 (edge_out)
template<int KSEL>
__device__ __forceinline__ void edge_mlp_tensor(
    char* sm, uint32_t smu, int tid,
    const int* __restrict__ ei, float* __restrict__ out, int E) {
    const int wid  = tid >> 5;
    const int lane = tid & 31;
    const uint32_t pB = smu + wid * WARP_PLANE;
    char* pC = sm + wid * WARP_PLANE;
    const int eb = blockIdx.x * 256 + wid * 32;
    constexpr int B1 = (KSEL == 0) ? R1B1 : R2B1;
    constexpr int B2 = (KSEL == 0) ? R1B2 : R2B2;
    const int c0base = (lane & 3) * 2;
    const uint2* __restrict__ gF = g_bfrag + KSEL * FRAG_CNT;

    __syncwarp();   // order stage_inputs stores before ldmatrix cross-lane reads

    // ---- layer 1: frag loaded once, applied to both mt tiles ----
    {
        uint32_t a0[2][4], a1[2][4];
#pragma unroll
        for (int mt = 0; mt < 2; ++mt) {
            ldsm4(a0[mt], a_addr(pB, mt, 0, lane));
            ldsm4(a1[mt], a_addr(pB, mt, 1, lane));
        }
        float acc[2][5][4];
#pragma unroll
        for (int nt = 0; nt < 5; ++nt) {
            const int c0 = nt * 8 + c0base;
            const float b0 = cP[B1 + c0], b1v = cP[B1 + c0 + 1];
            const uint2 F0 = __ldg(&gF[(0 * 5 + nt) * 32 + lane]);
            const uint2 F1 = __ldg(&gF[(1 * 5 + nt) * 32 + lane]);
#pragma unroll
            for (int mt = 0; mt < 2; ++mt) {
                acc[mt][nt][0] = b0; acc[mt][nt][1] = b1v;
                acc[mt][nt][2] = b0; acc[mt][nt][3] = b1v;
                mma16816(acc[mt][nt], a0[mt], F0.x, F0.y);
                mma16816(acc[mt][nt], a1[mt], F1.x, F1.y);
            }
        }
        // epilogue: relu + fp16 split -> h1 as [hi(40)|lo(40)]
#pragma unroll
        for (int mt = 0; mt < 2; ++mt) {
            const int rA = mt * 16 + (lane >> 2);
            char* r0 = pC + rA * ROWB;
            char* r8 = pC + (rA + 8) * ROWB;
#pragma unroll
            for (int nt = 0; nt < 5; ++nt) {
                const int c0 = nt * 8 + c0base;
                uint32_t h, l;
                split2h(fmaxf(acc[mt][nt][0], 0.f), fmaxf(acc[mt][nt][1], 0.f), h, l);
                *(uint32_t*)(r0 + 2 * c0)      = h;
                *(uint32_t*)(r0 + 80 + 2 * c0) = l;
                split2h(fmaxf(acc[mt][nt][2], 0.f), fmaxf(acc[mt][nt][3], 0.f), h, l);
                *(uint32_t*)(r8 + 2 * c0)      = h;
                *(uint32_t*)(r8 + 80 + 2 * c0) = l;
            }
        }
    }
    __syncwarp();

    // ---- layer 2: a-tiles loaded per-kt (low live regs) ----
    float acc2[2][5][4];
#pragma unroll
    for (int nt = 0; nt < 5; ++nt) {
        const int c0 = nt * 8 + c0base;
        const float b0 = cP[B2 + c0], b1v = cP[B2 + c0 + 1];
#pragma unroll
        for (int mt = 0; mt < 2; ++mt) {
            acc2[mt][nt][0] = b0; acc2[mt][nt][1] = b1v;
            acc2[mt][nt][2] = b0; acc2[mt][nt][3] = b1v;
        }
    }
#pragma unroll
    for (int kt = 0; kt < 5; ++kt) {
        uint32_t aA[4], aB[4];
        ldsm4(aA, a_addr(pB, 0, kt, lane));
        ldsm4(aB, a_addr(pB, 1, kt, lane));
#pragma unroll
        for (int nt = 0; nt < 5; ++nt) {
            const uint2 F = __ldg(&gF[((2 + kt) * 5 + nt) * 32 + lane]);
            mma16816(acc2[0][nt], aA, F.x, F.y);
            mma16816(acc2[1][nt], aB, F.x, F.y);
        }
        if (kt < 3) {
#pragma unroll
            for (int nt = 0; nt < 5; ++nt) {
                const uint2 F = __ldg(&gF[((7 + kt) * 5 + nt) * 32 + lane]);
                mma16816(acc2[0][nt], aA, F.x, F.y);
                mma16816(acc2[1][nt], aB, F.x, F.y);
            }
        }
    }

    // ---- layer 3 + writeback ----
#pragma unroll
    for (int mt = 0; mt < 2; ++mt) {
        if (KSEL == 0) {
            float p[8] = {0.f, 0.f, 0.f, 0.f, 0.f, 0.f, 0.f, 0.f};
#pragma unroll
            for (int nt = 0; nt < 5; ++nt) {
                const int c0 = nt * 8 + c0base;
                const float v0 = fmaxf(acc2[mt][nt][0], 0.f);
                const float v1 = fmaxf(acc2[mt][nt][1], 0.f);
                const float v2 = fmaxf(acc2[mt][nt][2], 0.f);
                const float v3 = fmaxf(acc2[mt][nt][3], 0.f);
#pragma unroll
                for (int j = 0; j < 4; ++j) {
                    const float w0 = cP[R1W3T + c0 * 4 + j];
                    const float w1 = cP[R1W3T + (c0 + 1) * 4 + j];
                    p[j]     += v0 * w0 + v1 * w1;
                    p[4 + j] += v2 * w0 + v3 * w1;
                }
            }
#pragma unroll
            for (int i = 0; i < 8; ++i) {
                p[i] += __shfl_xor_sync(0xffffffffu, p[i], 1);
                p[i] += __shfl_xor_sync(0xffffffffu, p[i], 2);
            }
            if ((lane & 3) == 0) {
                const int rA = mt * 16 + (lane >> 2);
                const int e1 = eb + rA, e2 = eb + rA + 8;
                if (e1 < E) {
                    const float o0 = p[0] + cP[R1B3 + 0], o1 = p[1] + cP[R1B3 + 1];
                    const float o2 = p[2] + cP[R1B3 + 2], o3 = p[3] + cP[R1B3 + 3];
                    const int d = ei[E + e1];
                    g_emsg[e1] = make_float4(o0, o1, o2, o3);
                    atomicAdd(&g_aggr[d * 4 + 0], o0);
                    atomicAdd(&g_aggr[d * 4 + 1], o1);
                    atomicAdd(&g_aggr[d * 4 + 2], o2);
                    atomicAdd(&g_aggr[d * 4 + 3], o3);
                }
                if (e2 < E) {
                    const float o0 = p[4] + cP[R1B3 + 0], o1 = p[5] + cP[R1B3 + 1];
                    const float o2 = p[6] + cP[R1B3 + 2], o3 = p[7] + cP[R1B3 + 3];
                    const int d = ei[E + e2];
                    g_emsg[e2] = make_float4(o0, o1, o2, o3);
                    atomicAdd(&g_aggr[d * 4 + 0], o0);
                    atomicAdd(&g_aggr[d * 4 + 1], o1);
                    atomicAdd(&g_aggr[d * 4 + 2], o2);
                    atomicAdd(&g_aggr[d * 4 + 3], o3);
                }
            }
        } else {
            float p0 = 0.f, p1 = 0.f;
#pragma unroll
            for (int nt = 0; nt < 5; ++nt) {
                const int c0 = nt * 8 + c0base;
                const float v0 = fmaxf(acc2[mt][nt][0], 0.f);
                const float v1 = fmaxf(acc2[mt][nt][1], 0.f);
                const float v2 = fmaxf(acc2[mt][nt][2], 0.f);
                const float v3 = fmaxf(acc2[mt][nt][3], 0.f);
                const float w0 = cP[R2W3 + c0], w1 = cP[R2W3 + c0 + 1];
                p0 += v0 * w0 + v1 * w1;
                p1 += v2 * w0 + v3 * w1;
            }
            p0 += __shfl_xor_sync(0xffffffffu, p0, 1);
            p0 += __shfl_xor_sync(0xffffffffu, p0, 2);
            p1 += __shfl_xor_sync(0xffffffffu, p1, 1);
            p1 += __shfl_xor_sync(0xffffffffu, p1, 2);
            if ((lane & 3) == 0) {
                const int rA = mt * 16 + (lane >> 2);
                const int e1 = eb + rA, e2 = eb + rA + 8;
                if (e1 < E) out[e1] = 1.f / (1.f + expf(-(p0 + cP[R2B3])));
                if (e2 < E) out[e2] = 1.f / (1.f + expf(-(p1 + cP[R2B3])));
            }
        }
    }
}

// Store inputs [hi10|lo10|hi10] (bytes 0-59) + zero ktile tail (bytes 60-63).
__device__ __forceinline__ void stage_inputs(char* sm, int tid, const float* in,
                                             bool valid) {
    const int wid  = tid >> 5;
    const int lane = tid & 31;
    char* r = sm + wid * WARP_PLANE + lane * ROWB;
    if (valid) {
#pragma unroll
        for (int j = 0; j < 5; ++j) {
            uint32_t h, l;
            split2h(in[2 * j], in[2 * j + 1], h, l);
            *(uint32_t*)(r + 4 * j)      = h;
            *(uint32_t*)(r + 20 + 4 * j) = l;
            *(uint32_t*)(r + 40 + 4 * j) = h;
        }
    } else {
#pragma unroll
        for (int j = 0; j < 15; ++j) *(uint32_t*)(r + 4 * j) = 0u;
    }
    *(uint32_t*)(r + 60) = 0u;
}

// ---------------------------------------------------------------------------
__global__ __launch_bounds__(256, 4)
void edge_msg_kernel(const int* __restrict__ ei,
                     const float* __restrict__ eattr, int E) {
    extern __shared__ char sm[];
    const uint32_t smu = smem_to_u32(sm);
    const int tid = threadIdx.x;
    const int e = blockIdx.x * 256 + tid;

    float in[10];
    if (e < E) {
        const int src = ei[e];
        const int dst = ei[E + e];
        const float4 xd = g_x4[dst];
        const float4 xs = g_x4[src];
        in[0] = xd.x; in[1] = xd.y; in[2] = xd.z;
        in[3] = xs.x; in[4] = xs.y; in[5] = xs.z;
        const float4 ea = reinterpret_cast<const float4*>(eattr)[e];
        in[6] = ea.x; in[7] = ea.y; in[8] = ea.z; in[9] = ea.w;
    }
    stage_inputs(sm, tid, in, e < E);
    edge_mlp_tensor<0>(sm, smu, tid, ei, nullptr, E);
}

__global__ __launch_bounds__(256, 4)
void edge_out_kernel(const int* __restrict__ ei,
                     float* __restrict__ out, int E) {
    extern __shared__ char sm[];
    const uint32_t smu = smem_to_u32(sm);
    const int tid = threadIdx.x;
    const int e = blockIdx.x * 256 + tid;

    float in[10];
    if (e < E) {
        const int src = ei[e];
        const int dst = ei[E + e];
        const float4 xd = g_xt4[dst];
        const float4 xs = g_xt4[src];
        in[0] = xd.x; in[1] = xd.y; in[2] = xd.z;
        in[3] = xs.x; in[4] = xs.y; in[5] = xs.z;
        const float4 em = g_emsg[e];
        in[6] = em.x; in[7] = em.y; in[8] = em.z; in[9] = em.w;
    }
    stage_inputs(sm, tid, in, e < E);
    edge_mlp_tensor<1>(sm, smu, tid, ei, out, E);
}

// ---------------------------------------------------------------------------
// Scalar node MLP (constant bank + FFMA2)
__device__ __forceinline__ void ffma2(unsigned long long& d, unsigned long long a,
                                      unsigned long long b) {
    asm("fma.rn.f32x2 %0, %1, %2, %0;" : "+l"(d) : "l"(a), "l"(b));
}
__device__ __forceinline__ unsigned long long dup2(float a) {
    unsigned long long r;
    asm("mov.b64 %0, {%1, %1};" : "=l"(r) : "f"(a));
    return r;
}
template<int IN, int OUT, int WOFF, int BOFF>
__device__ __forceinline__ void denseC(const float* in, float* out) {
    unsigned long long acc[OUT / 2];
#pragma unroll
    for (int j2 = 0; j2 < OUT / 2; ++j2)
        acc[j2] = *reinterpret_cast<const unsigned long long*>(cP + BOFF + 2 * j2);
#pragma unroll
    for (int k = 0; k < IN; ++k) {
        const unsigned long long a2 = dup2(in[k]);
#pragma unroll
        for (int j2 = 0; j2 < OUT / 2; ++j2)
            ffma2(acc[j2], a2,
                  *reinterpret_cast<const unsigned long long*>(cP + WOFF + k * OUT + 2 * j2));
    }
#pragma unroll
    for (int j2 = 0; j2 < OUT / 2; ++j2) {
        float lo, hi;
        asm("mov.b64 {%0, %1}, %2;" : "=f"(lo), "=f"(hi) : "l"(acc[j2]));
        out[2 * j2] = lo; out[2 * j2 + 1] = hi;
    }
}
template<int N>
__device__ __forceinline__ void relu_(float* v) {
#pragma unroll
    for (int i = 0; i < N; ++i) v[i] = fmaxf(v[i], 0.f);
}

__global__ __launch_bounds__(256)
void node_kernel(int N) {
    const int n = blockIdx.x * 256 + threadIdx.x;
    if (n >= N) return;
    float in[7];
    const float4 xn = g_x4[n];
    in[0] = xn.x; in[1] = xn.y; in[2] = xn.z;
    const float4 ag = reinterpret_cast<const float4*>(g_aggr)[n];
    in[3] = ag.x; in[4] = ag.y; in[5] = ag.z; in[6] = ag.w;
    float h1[40]; denseC<7, 40, OW1T, OB1>(in, h1); relu_<40>(h1);
    float h2[40]; denseC<40, 40, OW2T, OB2>(h1, h2); relu_<40>(h2);
    float o[4];   denseC<40, 4,  OW3T, OB3>(h2, o);
    g_xt4[n] = make_float4(o[0], o[1], o[2], 0.f);
}

// ---------------------------------------------------------------------------
// Prep: constants + composite B fragments + zero g_aggr + padded g_x4.
__device__ __forceinline__ float f16hi(float v) {
    return __half2float(__float2half_rn(v));
}

__global__ void prep_params_kernel(
    const float* __restrict__ x,
    const float* __restrict__ r1w1, const float* __restrict__ r1b1,
    const float* __restrict__ r1w2, const float* __restrict__ r1b2,
    const float* __restrict__ r1w3, const float* __restrict__ r1b3,
    const float* __restrict__ ow1,  const float* __restrict__ ob1,
    const float* __restrict__ ow2,  const float* __restrict__ ob2,
    const float* __restrict__ ow3,  const float* __restrict__ ob3,
    const float* __restrict__ r2w1, const float* __restrict__ r2b1,
    const float* __restrict__ r2w2, const float* __restrict__ r2b2,
    const float* __restrict__ r2w3, const float* __restrict__ r2b3,
    int Nnodes) {
    const int t = blockIdx.x * blockDim.x + threadIdx.x;
    const int S = gridDim.x * blockDim.x;

    for (int i = t; i < Nnodes * 4; i += S) g_aggr[i] = 0.f;
    for (int i = t; i < Nnodes; i += S)
        g_x4[i] = make_float4(x[3 * i], x[3 * i + 1], x[3 * i + 2], 0.f);

    for (int i = t; i < 400;  i += S) { int j = i / 10, k = i % 10; g_cparams[R1W1T + k * 40 + j] = r1w1[i]; }
    for (int i = t; i < 1600; i += S) { int j = i / 40, k = i % 40; g_cparams[R1W2T + k * 40 + j] = r1w2[i]; }
    for (int i = t; i < 160;  i += S) { int j = i / 40, k = i % 40; g_cparams[R1W3T + k * 4 + j]  = r1w3[i]; }
    for (int i = t; i < 280;  i += S) { int j = i / 7,  k = i % 7;  g_cparams[OW1T  + k * 40 + j] = ow1[i];  }
    for (int i = t; i < 1600; i += S) { int j = i / 40, k = i % 40; g_cparams[OW2T  + k * 40 + j] = ow2[i];  }
    for (int i = t; i < 160;  i += S) { int k = i / 4,  j = i % 4;  g_cparams[OW3T + i] = (j < 3) ? ow3[j * 40 + k] : 0.f; }
    for (int i = t; i < 400;  i += S) { int j = i / 10, k = i % 10; g_cparams[R2W1T + k * 40 + j] = r2w1[i]; }
    for (int i = t; i < 1600; i += S) { int j = i / 40, k = i % 40; g_cparams[R2W2T + k * 40 + j] = r2w2[i]; }
    for (int i = t; i < 40;   i += S) {
        g_cparams[R2W3 + i] = r2w3[i];
        g_cparams[R1B1 + i] = r1b1[i]; g_cparams[R1B2 + i] = r1b2[i];
        g_cparams[OB1  + i] = ob1[i];  g_cparams[OB2  + i] = ob2[i];
        g_cparams[R2B1 + i] = r2b1[i]; g_cparams[R2B2 + i] = r2b2[i];
    }
    for (int i = t; i < 4; i += S) {
        g_cparams[R1B3 + i] = r1b3[i];
        g_cparams[OB3  + i] = (i < 3) ? ob3[i] : 0.f;
    }
    if (t == 0) { g_cparams[R2B3] = r2b3[0]; g_cparams[R2B3 + 1] = 0.f; }

    // Composite B fragment tables (same mapping as R9/R10/R12/R13).
    for (int idx = t; idx < 2 * FRAG_CNT; idx += S) {
        const int ker  = idx / FRAG_CNT;
        const int rem  = idx % FRAG_CNT;
        const int f    = rem / 160;
        const int nt   = (rem % 160) / 32;
        const int lane = rem % 32;
        const float* W1 = ker ? r2w1 : r1w1;
        const float* W2 = ker ? r2w2 : r1w2;
        const int n  = nt * 8 + (lane >> 2);
        const int kb = (lane & 3) * 2;
        const int ksl[4] = {kb, kb + 1, kb + 8, kb + 9};
        float v[4];
#pragma unroll
        for (int i = 0; i < 4; ++i) {
            float val = 0.f;
            if (f < 2) {                         // layer1: [Wh;Wh;Wl]
                const int kc = f * 16 + ksl[i];
                if (kc < 10)      { const float w = W1[n * 10 + kc];      val = f16hi(w); }
                else if (kc < 20) { const float w = W1[n * 10 + kc - 10]; val = f16hi(w); }
                else if (kc < 30) { const float w = W1[n * 10 + kc - 20]; val = w - f16hi(w); }
            } else if (f < 7) {                  // layer2 pass1: [Wh;Wh]
                const int kc = (f - 2) * 16 + ksl[i];
                if (kc < 40)      { const float w = W2[n * 40 + kc];      val = f16hi(w); }
                else              { const float w = W2[n * 40 + kc - 40]; val = f16hi(w); }
            } else {                             // layer2 pass2: [Wl;0]
                const int kc = (f - 7) * 16 + ksl[i];
                if (kc < 40)      { const float w = W2[n * 40 + kc];      val = w - f16hi(w); }
            }
            v[i] = val;
        }
        uint2 F;
        F.x = h2pack(v[0], v[1]);
        F.y = h2pack(v[2], v[3]);
        g_bfrag[idx] = F;
    }
}

// ---------------------------------------------------------------------------
extern "C" void kernel_launch(void* const* d_in, const int* in_sizes, int n_in,
                              void* d_out, int out_size) {
    const float* x     = (const float*)d_in[0];
    const int*   ei    = (const int*)d_in[1];
    const float* eattr = (const float*)d_in[2];
    const float *r1w1 = (const float*)d_in[3],  *r1b1 = (const float*)d_in[4];
    const float *r1w2 = (const float*)d_in[5],  *r1b2 = (const float*)d_in[6];
    const float *r1w3 = (const float*)d_in[7],  *r1b3 = (const float*)d_in[8];
    const float *ow1  = (const float*)d_in[9],  *ob1  = (const float*)d_in[10];
    const float *ow2  = (const float*)d_in[11], *ob2  = (const float*)d_in[12];
    const float *ow3  = (const float*)d_in[13], *ob3  = (const float*)d_in[14];
    const float *r2w1 = (const float*)d_in[15], *r2b1 = (const float*)d_in[16];
    const float *r2w2 = (const float*)d_in[17], *r2b2 = (const float*)d_in[18];
    const float *r2w3 = (const float*)d_in[19], *r2b3 = (const float*)d_in[20];

    const int N = in_sizes[0] / 3;
    const int E = in_sizes[2] / 4;

    cudaFuncSetAttribute(edge_msg_kernel,
                         cudaFuncAttributeMaxDynamicSharedMemorySize, SMEM_TOTAL);
    cudaFuncSetAttribute(edge_out_kernel,
                         cudaFuncAttributeMaxDynamicSharedMemorySize, SMEM_TOTAL);

    prep_params_kernel<<<1600, 256>>>(x,
                                      r1w1, r1b1, r1w2, r1b2, r1w3, r1b3,
                                      ow1, ob1, ow2, ob2, ow3, ob3,
                                      r2w1, r2b1, r2w2, r2b2, r2w3, r2b3, N);
    void* src = nullptr;
    cudaGetSymbolAddress(&src, g_cparams);
    cudaMemcpyToSymbolAsync(cP, src, CP_TOTAL * sizeof(float), 0,
                            cudaMemcpyDeviceToDevice, 0);

    const int eblk = (E + 255) / 256;
    edge_msg_kernel<<<eblk, 256, SMEM_TOTAL>>>(ei, eattr, E);
    node_kernel<<<(N + 255) / 256, 256>>>(N);
    edge_out_kernel<<<eblk, 256, SMEM_TOTAL>>>(ei, (float*)d_out, E);
}

// round 15
// speedup vs baseline: 1.1382x; 1.1382x over previous
#include <cuda_runtime.h>
#include <cuda_fp16.h>
#include <math.h>
#include <stdint.h>

// ---------------------------------------------------------------------------
// InteractionNetwork, HMMA (mma.sync m16n8k16 f16), base-sm_100 target.
// R15: R14 occupancy experiment proved the legacy HMMA pipe is the saturated
// resource (dur invariant to occ 23->47%). Spend precision margin (rel_err
// 3.9e-8 vs 1e-3 threshold): drop layer-2 pass2 (Ahi*Bl weight-lo correction,
// 30% of all mmas). Layer 2 = AhiBh + AloBh; expected rel_err ~1e-4.
// ---------------------------------------------------------------------------

constexpr int N_MAX = 100000;
constexpr int E_MAX = 2000000;

__device__ float4 g_emsg[E_MAX];
__device__ float  g_aggr[N_MAX * 4];
__device__ float4 g_x4 [N_MAX];    // padded copy of x
__device__ float4 g_xt4[N_MAX];    // padded x_tilde

// --- constant bank ----------------------------------------------------------
constexpr int R1W1T = 0;
constexpr int R1B1  = 400;
constexpr int R1W2T = 440;
constexpr int R1B2  = 2040;
constexpr int R1W3T = 2080;   // [40][4]
constexpr int R1B3  = 2240;
constexpr int OW1T  = 2244;
constexpr int OB1   = 2524;
constexpr int OW2T  = 2564;
constexpr int OB2   = 4164;
constexpr int OW3T  = 4204;
constexpr int OB3   = 4364;
constexpr int R2W1T = 4368;
constexpr int R2B1  = 4768;
constexpr int R2W2T = 4808;
constexpr int R2B2  = 6408;
constexpr int R2W3  = 6448;
constexpr int R2B3  = 6488;
constexpr int CP_TOTAL = 6496;

__constant__ float cP[CP_TOTAL];
__device__   float g_cparams[CP_TOTAL];

// B fragments: [kernel(2)][f(10)][nt(5)][lane(32)] uint2 {b0,b1}
// (f 7-9 retained in the table but unused since R15 dropped pass2)
constexpr int FRAG_CNT = 10 * 5 * 32;        // 1600 uint2 per kernel
__device__ uint2 g_bfrag[2 * FRAG_CNT];

// --- helpers ----------------------------------------------------------------
__device__ __forceinline__ uint32_t smem_to_u32(const void* p) {
    uint32_t a;
    asm("{ .reg .u64 t; cvta.to.shared.u64 t, %1; cvt.u32.u64 %0, t; }"
        : "=r"(a) : "l"(p));
    return a;
}

__device__ __forceinline__ uint32_t h2pack(float a, float b) {
    __half2 h;
    h.x = __float2half_rn(a);
    h.y = __float2half_rn(b);
    return *reinterpret_cast<uint32_t*>(&h);
}

__device__ __forceinline__ void split2h(float v0, float v1,
                                        uint32_t& hi, uint32_t& lo) {
    const __half h0 = __float2half_rn(v0);
    const __half h1 = __float2half_rn(v1);
    __half2 H; H.x = h0; H.y = h1;
    __half2 L;
    L.x = __float2half_rn(v0 - __half2float(h0));
    L.y = __float2half_rn(v1 - __half2float(h1));
    hi = *reinterpret_cast<uint32_t*>(&H);
    lo = *reinterpret_cast<uint32_t*>(&L);
}

__device__ __forceinline__ void ldsm4(uint32_t* r, uint32_t addr) {
    asm volatile("ldmatrix.sync.aligned.m8n8.x4.shared.b16 {%0,%1,%2,%3}, [%4];"
                 : "=r"(r[0]), "=r"(r[1]), "=r"(r[2]), "=r"(r[3]) : "r"(addr));
}

__device__ __forceinline__ void mma16816(float* c, const uint32_t* a,
                                         uint32_t b0, uint32_t b1) {
    asm volatile("mma.sync.aligned.m16n8k16.row.col.f32.f16.f16.f32 "
                 "{%0,%1,%2,%3}, {%4,%5,%6,%7}, {%8,%9}, {%0,%1,%2,%3};"
                 : "+f"(c[0]), "+f"(c[1]), "+f"(c[2]), "+f"(c[3])
                 : "r"(a[0]), "r"(a[1]), "r"(a[2]), "r"(a[3]), "r"(b0), "r"(b1));
}

// smem: single A plane [8 warps][32 rows][176B]
constexpr int ROWB = 176;
constexpr int WARP_PLANE = 32 * ROWB;        // 5632
constexpr int SMEM_TOTAL = 8 * WARP_PLANE;   // 45056

__device__ __forceinline__ uint32_t a_addr(uint32_t base, int mt, int kt, int lane) {
    const int g = lane >> 3;
    const int row = mt * 16 + (lane & 7) + ((g & 1) << 3);
    const int col = ((g >> 1) << 4) + kt * 32;
    return base + row * ROWB + col;
}

// ---------------------------------------------------------------------------
// KSEL: 0 = R1 (edge_msg), 1 = R2 (edge_out)
template<int KSEL>
__device__ __forceinline__ void edge_mlp_tensor(
    char* sm, uint32_t smu, int tid,
    const int* __restrict__ ei, float* __restrict__ out, int E) {
    const int wid  = tid >> 5;
    const int lane = tid & 31;
    const uint32_t pB = smu + wid * WARP_PLANE;
    char* pC = sm + wid * WARP_PLANE;
    const int eb = blockIdx.x * 256 + wid * 32;
    constexpr int B1 = (KSEL == 0) ? R1B1 : R2B1;
    constexpr int B2 = (KSEL == 0) ? R1B2 : R2B2;
    const int c0base = (lane & 3) * 2;
    const uint2* __restrict__ gF = g_bfrag + KSEL * FRAG_CNT;

    __syncwarp();   // order stage_inputs stores before ldmatrix cross-lane reads

    // ---- layer 1: 2 composite ktiles ([hi10|lo10|hi10] x [Wh;Wh;Wl]) ----
    {
        uint32_t a0[2][4], a1[2][4];
#pragma unroll
        for (int mt = 0; mt < 2; ++mt) {
            ldsm4(a0[mt], a_addr(pB, mt, 0, lane));
            ldsm4(a1[mt], a_addr(pB, mt, 1, lane));
        }
        float acc[2][5][4];
#pragma unroll
        for (int nt = 0; nt < 5; ++nt) {
            const int c0 = nt * 8 + c0base;
            const float b0 = cP[B1 + c0], b1v = cP[B1 + c0 + 1];
            const uint2 F0 = __ldg(&gF[(0 * 5 + nt) * 32 + lane]);
            const uint2 F1 = __ldg(&gF[(1 * 5 + nt) * 32 + lane]);
#pragma unroll
            for (int mt = 0; mt < 2; ++mt) {
                acc[mt][nt][0] = b0; acc[mt][nt][1] = b1v;
                acc[mt][nt][2] = b0; acc[mt][nt][3] = b1v;
                mma16816(acc[mt][nt], a0[mt], F0.x, F0.y);
                mma16816(acc[mt][nt], a1[mt], F1.x, F1.y);
            }
        }
        // epilogue: relu + fp16 split -> h1 as [hi(40)|lo(40)]
#pragma unroll
        for (int mt = 0; mt < 2; ++mt) {
            const int rA = mt * 16 + (lane >> 2);
            char* r0 = pC + rA * ROWB;
            char* r8 = pC + (rA + 8) * ROWB;
#pragma unroll
            for (int nt = 0; nt < 5; ++nt) {
                const int c0 = nt * 8 + c0base;
                uint32_t h, l;
                split2h(fmaxf(acc[mt][nt][0], 0.f), fmaxf(acc[mt][nt][1], 0.f), h, l);
                *(uint32_t*)(r0 + 2 * c0)      = h;
                *(uint32_t*)(r0 + 80 + 2 * c0) = l;
                split2h(fmaxf(acc[mt][nt][2], 0.f), fmaxf(acc[mt][nt][3], 0.f), h, l);
                *(uint32_t*)(r8 + 2 * c0)      = h;
                *(uint32_t*)(r8 + 80 + 2 * c0) = l;
            }
        }
    }
    __syncwarp();

    // ---- layer 2: pass1 only (AhiBh + AloBh via [Wh;Wh]) — pass2 dropped ----
    float acc2[2][5][4];
#pragma unroll
    for (int nt = 0; nt < 5; ++nt) {
        const int c0 = nt * 8 + c0base;
        const float b0 = cP[B2 + c0], b1v = cP[B2 + c0 + 1];
#pragma unroll
        for (int mt = 0; mt < 2; ++mt) {
            acc2[mt][nt][0] = b0; acc2[mt][nt][1] = b1v;
            acc2[mt][nt][2] = b0; acc2[mt][nt][3] = b1v;
        }
    }
#pragma unroll
    for (int kt = 0; kt < 5; ++kt) {
        uint32_t aA[4], aB[4];
        ldsm4(aA, a_addr(pB, 0, kt, lane));
        ldsm4(aB, a_addr(pB, 1, kt, lane));
#pragma unroll
        for (int nt = 0; nt < 5; ++nt) {
            const uint2 F = __ldg(&gF[((2 + kt) * 5 + nt) * 32 + lane]);
            mma16816(acc2[0][nt], aA, F.x, F.y);
            mma16816(acc2[1][nt], aB, F.x, F.y);
        }
    }

    // ---- layer 3 + writeback ----
#pragma unroll
    for (int mt = 0; mt < 2; ++mt) {
        if (KSEL == 0) {
            float p[8] = {0.f, 0.f, 0.f, 0.f, 0.f, 0.f, 0.f, 0.f};
#pragma unroll
            for (int nt = 0; nt < 5; ++nt) {
                const int c0 = nt * 8 + c0base;
                const float v0 = fmaxf(acc2[mt][nt][0], 0.f);
                const float v1 = fmaxf(acc2[mt][nt][1], 0.f);
                const float v2 = fmaxf(acc2[mt][nt][2], 0.f);
                const float v3 = fmaxf(acc2[mt][nt][3], 0.f);
#pragma unroll
                for (int j = 0; j < 4; ++j) {
                    const float w0 = cP[R1W3T + c0 * 4 + j];
                    const float w1 = cP[R1W3T + (c0 + 1) * 4 + j];
                    p[j]     += v0 * w0 + v1 * w1;
                    p[4 + j] += v2 * w0 + v3 * w1;
                }
            }
#pragma unroll
            for (int i = 0; i < 8; ++i) {
                p[i] += __shfl_xor_sync(0xffffffffu, p[i], 1);
                p[i] += __shfl_xor_sync(0xffffffffu, p[i], 2);
            }
            if ((lane & 3) == 0) {
                const int rA = mt * 16 + (lane >> 2);
                const int e1 = eb + rA, e2 = eb + rA + 8;
                if (e1 < E) {
                    const float o0 = p[0] + cP[R1B3 + 0], o1 = p[1] + cP[R1B3 + 1];
                    const float o2 = p[2] + cP[R1B3 + 2], o3 = p[3] + cP[R1B3 + 3];
                    const int d = ei[E + e1];
                    g_emsg[e1] = make_float4(o0, o1, o2, o3);
                    atomicAdd(&g_aggr[d * 4 + 0], o0);
                    atomicAdd(&g_aggr[d * 4 + 1], o1);
                    atomicAdd(&g_aggr[d * 4 + 2], o2);
                    atomicAdd(&g_aggr[d * 4 + 3], o3);
                }
                if (e2 < E) {
                    const float o0 = p[4] + cP[R1B3 + 0], o1 = p[5] + cP[R1B3 + 1];
                    const float o2 = p[6] + cP[R1B3 + 2], o3 = p[7] + cP[R1B3 + 3];
                    const int d = ei[E + e2];
                    g_emsg[e2] = make_float4(o0, o1, o2, o3);
                    atomicAdd(&g_aggr[d * 4 + 0], o0);
                    atomicAdd(&g_aggr[d * 4 + 1], o1);
                    atomicAdd(&g_aggr[d * 4 + 2], o2);
                    atomicAdd(&g_aggr[d * 4 + 3], o3);
                }
            }
        } else {
            float p0 = 0.f, p1 = 0.f;
#pragma unroll
            for (int nt = 0; nt < 5; ++nt) {
                const int c0 = nt * 8 + c0base;
                const float v0 = fmaxf(acc2[mt][nt][0], 0.f);
                const float v1 = fmaxf(acc2[mt][nt][1], 0.f);
                const float v2 = fmaxf(acc2[mt][nt][2], 0.f);
                const float v3 = fmaxf(acc2[mt][nt][3], 0.f);
                const float w0 = cP[R2W3 + c0], w1 = cP[R2W3 + c0 + 1];
                p0 += v0 * w0 + v1 * w1;
                p1 += v2 * w0 + v3 * w1;
            }
            p0 += __shfl_xor_sync(0xffffffffu, p0, 1);
            p0 += __shfl_xor_sync(0xffffffffu, p0, 2);
            p1 += __shfl_xor_sync(0xffffffffu, p1, 1);
            p1 += __shfl_xor_sync(0xffffffffu, p1, 2);
            if ((lane & 3) == 0) {
                const int rA = mt * 16 + (lane >> 2);
                const int e1 = eb + rA, e2 = eb + rA + 8;
                if (e1 < E) out[e1] = 1.f / (1.f + expf(-(p0 + cP[R2B3])));
                if (e2 < E) out[e2] = 1.f / (1.f + expf(-(p1 + cP[R2B3])));
            }
        }
    }
}

// Store inputs [hi10|lo10|hi10] (bytes 0-59) + zero ktile tail (bytes 60-63).
__device__ __forceinline__ void stage_inputs(char* sm, int tid, const float* in,
                                             bool valid) {
    const int wid  = tid >> 5;
    const int lane = tid & 31;
    char* r = sm + wid * WARP_PLANE + lane * ROWB;
    if (valid) {
#pragma unroll
        for (int j = 0; j < 5; ++j) {
            uint32_t h, l;
            split2h(in[2 * j], in[2 * j + 1], h, l);
            *(uint32_t*)(r + 4 * j)      = h;
            *(uint32_t*)(r + 20 + 4 * j) = l;
            *(uint32_t*)(r + 40 + 4 * j) = h;
        }
    } else {
#pragma unroll
        for (int j = 0; j < 15; ++j) *(uint32_t*)(r + 4 * j) = 0u;
    }
    *(uint32_t*)(r + 60) = 0u;
}

// ---------------------------------------------------------------------------
__global__ __launch_bounds__(256, 4)
void edge_msg_kernel(const int* __restrict__ ei,
                     const float* __restrict__ eattr, int E) {
    extern __shared__ char sm[];
    const uint32_t smu = smem_to_u32(sm);
    const int tid = threadIdx.x;
    const int e = blockIdx.x * 256 + tid;

    float in[10];
    if (e < E) {
        const int src = ei[e];
        const int dst = ei[E + e];
        const float4 xd = g_x4[dst];
        const float4 xs = g_x4[src];
        in[0] = xd.x; in[1] = xd.y; in[2] = xd.z;
        in[3] = xs.x; in[4] = xs.y; in[5] = xs.z;
        const float4 ea = reinterpret_cast<const float4*>(eattr)[e];
        in[6] = ea.x; in[7] = ea.y; in[8] = ea.z; in[9] = ea.w;
    }
    stage_inputs(sm, tid, in, e < E);
    edge_mlp_tensor<0>(sm, smu, tid, ei, nullptr, E);
}

__global__ __launch_bounds__(256, 4)
void edge_out_kernel(const int* __restrict__ ei,
                     float* __restrict__ out, int E) {
    extern __shared__ char sm[];
    const uint32_t smu = smem_to_u32(sm);
    const int tid = threadIdx.x;
    const int e = blockIdx.x * 256 + tid;

    float in[10];
    if (e < E) {
        const int src = ei[e];
        const int dst = ei[E + e];
        const float4 xd = g_xt4[dst];
        const float4 xs = g_xt4[src];
        in[0] = xd.x; in[1] = xd.y; in[2] = xd.z;
        in[3] = xs.x; in[4] = xs.y; in[5] = xs.z;
        const float4 em = g_emsg[e];
        in[6] = em.x; in[7] = em.y; in[8] = em.z; in[9] = em.w;
    }
    stage_inputs(sm, tid, in, e < E);
    edge_mlp_tensor<1>(sm, smu, tid, ei, out, E);
}

// ---------------------------------------------------------------------------
// Scalar node MLP (constant bank + FFMA2)
__device__ __forceinline__ void ffma2(unsigned long long& d, unsigned long long a,
                                      unsigned long long b) {
    asm("fma.rn.f32x2 %0, %1, %2, %0;" : "+l"(d) : "l"(a), "l"(b));
}
__device__ __forceinline__ unsigned long long dup2(float a) {
    unsigned long long r;
    asm("mov.b64 %0, {%1, %1};" : "=l"(r) : "f"(a));
    return r;
}
template<int IN, int OUT, int WOFF, int BOFF>
__device__ __forceinline__ void denseC(const float* in, float* out) {
    unsigned long long acc[OUT / 2];
#pragma unroll
    for (int j2 = 0; j2 < OUT / 2; ++j2)
        acc[j2] = *reinterpret_cast<const unsigned long long*>(cP + BOFF + 2 * j2);
#pragma unroll
    for (int k = 0; k < IN; ++k) {
        const unsigned long long a2 = dup2(in[k]);
#pragma unroll
        for (int j2 = 0; j2 < OUT / 2; ++j2)
            ffma2(acc[j2], a2,
                  *reinterpret_cast<const unsigned long long*>(cP + WOFF + k * OUT + 2 * j2));
    }
#pragma unroll
    for (int j2 = 0; j2 < OUT / 2; ++j2) {
        float lo, hi;
        asm("mov.b64 {%0, %1}, %2;" : "=f"(lo), "=f"(hi) : "l"(acc[j2]));
        out[2 * j2] = lo; out[2 * j2 + 1] = hi;
    }
}
template<int N>
__device__ __forceinline__ void relu_(float* v) {
#pragma unroll
    for (int i = 0; i < N; ++i) v[i] = fmaxf(v[i], 0.f);
}

__global__ __launch_bounds__(256)
void node_kernel(int N) {
    const int n = blockIdx.x * 256 + threadIdx.x;
    if (n >= N) return;
    float in[7];
    const float4 xn = g_x4[n];
    in[0] = xn.x; in[1] = xn.y; in[2] = xn.z;
    const float4 ag = reinterpret_cast<const float4*>(g_aggr)[n];
    in[3] = ag.x; in[4] = ag.y; in[5] = ag.z; in[6] = ag.w;
    float h1[40]; denseC<7, 40, OW1T, OB1>(in, h1); relu_<40>(h1);
    float h2[40]; denseC<40, 40, OW2T, OB2>(h1, h2); relu_<40>(h2);
    float o[4];   denseC<40, 4,  OW3T, OB3>(h2, o);
    g_xt4[n] = make_float4(o[0], o[1], o[2], 0.f);
}

// ---------------------------------------------------------------------------
// Prep: constants + composite B fragments + zero g_aggr + padded g_x4.
__device__ __forceinline__ float f16hi(float v) {
    return __half2float(__float2half_rn(v));
}

__global__ void prep_params_kernel(
    const float* __restrict__ x,
    const float* __restrict__ r1w1, const float* __restrict__ r1b1,
    const float* __restrict__ r1w2, const float* __restrict__ r1b2,
    const float* __restrict__ r1w3, const float* __restrict__ r1b3,
    const float* __restrict__ ow1,  const float* __restrict__ ob1,
    const float* __restrict__ ow2,  const float* __restrict__ ob2,
    const float* __restrict__ ow3,  const float* __restrict__ ob3,
    const float* __restrict__ r2w1, const float* __restrict__ r2b1,
    const float* __restrict__ r2w2, const float* __restrict__ r2b2,
    const float* __restrict__ r2w3, const float* __restrict__ r2b3,
    int Nnodes) {
    const int t = blockIdx.x * blockDim.x + threadIdx.x;
    const int S = gridDim.x * blockDim.x;

    for (int i = t; i < Nnodes * 4; i += S) g_aggr[i] = 0.f;
    for (int i = t; i < Nnodes; i += S)
        g_x4[i] = make_float4(x[3 * i], x[3 * i + 1], x[3 * i + 2], 0.f);

    for (int i = t; i < 400;  i += S) { int j = i / 10, k = i % 10; g_cparams[R1W1T + k * 40 + j] = r1w1[i]; }
    for (int i = t; i < 1600; i += S) { int j = i / 40, k = i % 40; g_cparams[R1W2T + k * 40 + j] = r1w2[i]; }
    for (int i = t; i < 160;  i += S) { int j = i / 40, k = i % 40; g_cparams[R1W3T + k * 4 + j]  = r1w3[i]; }
    for (int i = t; i < 280;  i += S) { int j = i / 7,  k = i % 7;  g_cparams[OW1T  + k * 40 + j] = ow1[i];  }
    for (int i = t; i < 1600; i += S) { int j = i / 40, k = i % 40; g_cparams[OW2T  + k * 40 + j] = ow2[i];  }
    for (int i = t; i < 160;  i += S) { int k = i / 4,  j = i % 4;  g_cparams[OW3T + i] = (j < 3) ? ow3[j * 40 + k] : 0.f; }
    for (int i = t; i < 400;  i += S) { int j = i / 10, k = i % 10; g_cparams[R2W1T + k * 40 + j] = r2w1[i]; }
    for (int i = t; i < 1600; i += S) { int j = i / 40, k = i % 40; g_cparams[R2W2T + k * 40 + j] = r2w2[i]; }
    for (int i = t; i < 40;   i += S) {
        g_cparams[R2W3 + i] = r2w3[i];
        g_cparams[R1B1 + i] = r1b1[i]; g_cparams[R1B2 + i] = r1b2[i];
        g_cparams[OB1  + i] = ob1[i];  g_cparams[OB2  + i] = ob2[i];
        g_cparams[R2B1 + i] = r2b1[i]; g_cparams[R2B2 + i] = r2b2[i];
    }
    for (int i = t; i < 4; i += S) {
        g_cparams[R1B3 + i] = r1b3[i];
        g_cparams[OB3  + i] = (i < 3) ? ob3[i] : 0.f;
    }
    if (t == 0) { g_cparams[R2B3] = r2b3[0]; g_cparams[R2B3 + 1] = 0.f; }

    // Composite B fragment tables (same mapping; f 7-9 written but unused).
    for (int idx = t; idx < 2 * FRAG_CNT; idx += S) {
        const int ker  = idx / FRAG_CNT;
        const int rem  = idx % FRAG_CNT;
        const int f    = rem / 160;
        const int nt   = (rem % 160) / 32;
        const int lane = rem % 32;
        const float* W1 = ker ? r2w1 : r1w1;
        const float* W2 = ker ? r2w2 : r1w2;
        const int n  = nt * 8 + (lane >> 2);
        const int kb = (lane & 3) * 2;
        const int ksl[4] = {kb, kb + 1, kb + 8, kb + 9};
        float v[4];
#pragma unroll
        for (int i = 0; i < 4; ++i) {
            float val = 0.f;
            if (f < 2) {                         // layer1: [Wh;Wh;Wl]
                const int kc = f * 16 + ksl[i];
                if (kc < 10)      { const float w = W1[n * 10 + kc];      val = f16hi(w); }
                else if (kc < 20) { const float w = W1[n * 10 + kc - 10]; val = f16hi(w); }
                else if (kc < 30) { const float w = W1[n * 10 + kc - 20]; val = w - f16hi(w); }
            } else if (f < 7) {                  // layer2 pass1: [Wh;Wh]
                const int kc = (f - 2) * 16 + ksl[i];
                if (kc < 40)      { const float w = W2[n * 40 + kc];      val = f16hi(w); }
                else              { const float w = W2[n * 40 + kc - 40]; val = f16hi(w); }
            } else {                             // layer2 pass2 (unused in R15)
                const int kc = (f - 7) * 16 + ksl[i];
                if (kc < 40)      { const float w = W2[n * 40 + kc];      val = w - f16hi(w); }
            }
            v[i] = val;
        }
        uint2 F;
        F.x = h2pack(v[0], v[1]);
        F.y = h2pack(v[2], v[3]);
        g_bfrag[idx] = F;
    }
}

// ---------------------------------------------------------------------------
extern "C" void kernel_launch(void* const* d_in, const int* in_sizes, int n_in,
                              void* d_out, int out_size) {
    const float* x     = (const float*)d_in[0];
    const int*   ei    = (const int*)d_in[1];
    const float* eattr = (const float*)d_in[2];
    const float *r1w1 = (const float*)d_in[3],  *r1b1 = (const float*)d_in[4];
    const float *r1w2 = (const float*)d_in[5],  *r1b2 = (const float*)d_in[6];
    const float *r1w3 = (const float*)d_in[7],  *r1b3 = (const float*)d_in[8];
    const float *ow1  = (const float*)d_in[9],  *ob1  = (const float*)d_in[10];
    const float *ow2  = (const float*)d_in[11], *ob2  = (const float*)d_in[12];
    const float *ow3  = (const float*)d_in[13], *ob3  = (const float*)d_in[14];
    const float *r2w1 = (const float*)d_in[15], *r2b1 = (const float*)d_in[16];
    const float *r2w2 = (const float*)d_in[17], *r2b2 = (const float*)d_in[18];
    const float *r2w3 = (const float*)d_in[19], *r2b3 = (const float*)d_in[20];

    const int N = in_sizes[0] / 3;
    const int E = in_sizes[2] / 4;

    cudaFuncSetAttribute(edge_msg_kernel,
                         cudaFuncAttributeMaxDynamicSharedMemorySize, SMEM_TOTAL);
    cudaFuncSetAttribute(edge_out_kernel,
                         cudaFuncAttributeMaxDynamicSharedMemorySize, SMEM_TOTAL);

    prep_params_kernel<<<1600, 256>>>(x,
                                      r1w1, r1b1, r1w2, r1b2, r1w3, r1b3,
                                      ow1, ob1, ow2, ob2, ow3, ob3,
                                      r2w1, r2b1, r2w2, r2b2, r2w3, r2b3, N);
    void* src = nullptr;
    cudaGetSymbolAddress(&src, g_cparams);
    cudaMemcpyToSymbolAsync(cP, src, CP_TOTAL * sizeof(float), 0,
                            cudaMemcpyDeviceToDevice, 0);

    const int eblk = (E + 255) / 256;
    edge_msg_kernel<<<eblk, 256, SMEM_TOTAL>>>(ei, eattr, E);
    node_kernel<<<(N + 255) / 256, 256>>>(N);
    edge_out_kernel<<<eblk, 256, SMEM_TOTAL>>>(ei, (float*)d_out, E);
}

// round 17
// speedup vs baseline: 1.3100x; 1.1509x over previous
#include <cuda_runtime.h>
#include <cuda_fp16.h>
#include <math.h>
#include <stdint.h>

// ---------------------------------------------------------------------------
// InteractionNetwork, HMMA (mma.sync m16n8k16 f16), base-sm_100 target.
// R17 = identical resubmit of R16 (container infra failure, no kernel signal).
// Layer 1 composite ([hi10|lo10|hi10] x [Wh;Wh;Wl], accurate h1); h1 stored
// plain fp16; layer 2 pure fp16 over K=48: mma/warp 70 -> 50, ldsm 14 -> 10,
// frag ldg 35 -> 25, epilogue STS halved, smem 45KB -> 28.7KB.
// Expected rel_err ~2-5e-6.
// ---------------------------------------------------------------------------

constexpr int N_MAX = 100000;
constexpr int E_MAX = 2000000;

__device__ float4 g_emsg[E_MAX];
__device__ float  g_aggr[N_MAX * 4];
__device__ float4 g_x4 [N_MAX];    // padded copy of x
__device__ float4 g_xt4[N_MAX];    // padded x_tilde

// --- constant bank ----------------------------------------------------------
constexpr int R1W1T = 0;
constexpr int R1B1  = 400;
constexpr int R1W2T = 440;
constexpr int R1B2  = 2040;
constexpr int R1W3T = 2080;   // [40][4]
constexpr int R1B3  = 2240;
constexpr int OW1T  = 2244;
constexpr int OB1   = 2524;
constexpr int OW2T  = 2564;
constexpr int OB2   = 4164;
constexpr int OW3T  = 4204;
constexpr int OB3   = 4364;
constexpr int R2W1T = 4368;
constexpr int R2B1  = 4768;
constexpr int R2W2T = 4808;
constexpr int R2B2  = 6408;
constexpr int R2W3  = 6448;
constexpr int R2B3  = 6488;
constexpr int CP_TOTAL = 6496;

__constant__ float cP[CP_TOTAL];
__device__   float g_cparams[CP_TOTAL];

// B fragments: [kernel(2)][f(10)][nt(5)][lane(32)] uint2 {b0,b1}
// f 0-1: layer1 composite ktiles; f 2-4: layer2 Wh (K=48, kc>=40 zero);
// f 5-9: unused (zeroed).
constexpr int FRAG_CNT = 10 * 5 * 32;        // 1600 uint2 per kernel
__device__ uint2 g_bfrag[2 * FRAG_CNT];

// --- helpers ----------------------------------------------------------------
__device__ __forceinline__ uint32_t smem_to_u32(const void* p) {
    uint32_t a;
    asm("{ .reg .u64 t; cvta.to.shared.u64 t, %1; cvt.u32.u64 %0, t; }"
        : "=r"(a) : "l"(p));
    return a;
}

__device__ __forceinline__ uint32_t h2pack(float a, float b) {
    __half2 h;
    h.x = __float2half_rn(a);
    h.y = __float2half_rn(b);
    return *reinterpret_cast<uint32_t*>(&h);
}

__device__ __forceinline__ void split2h(float v0, float v1,
                                        uint32_t& hi, uint32_t& lo) {
    const __half h0 = __float2half_rn(v0);
    const __half h1 = __float2half_rn(v1);
    __half2 H; H.x = h0; H.y = h1;
    __half2 L;
    L.x = __float2half_rn(v0 - __half2float(h0));
    L.y = __float2half_rn(v1 - __half2float(h1));
    hi = *reinterpret_cast<uint32_t*>(&H);
    lo = *reinterpret_cast<uint32_t*>(&L);
}

__device__ __forceinline__ void ldsm4(uint32_t* r, uint32_t addr) {
    asm volatile("ldmatrix.sync.aligned.m8n8.x4.shared.b16 {%0,%1,%2,%3}, [%4];"
                 : "=r"(r[0]), "=r"(r[1]), "=r"(r[2]), "=r"(r[3]) : "r"(addr));
}

__device__ __forceinline__ void mma16816(float* c, const uint32_t* a,
                                         uint32_t b0, uint32_t b1) {
    asm volatile("mma.sync.aligned.m16n8k16.row.col.f32.f16.f16.f32 "
                 "{%0,%1,%2,%3}, {%4,%5,%6,%7}, {%8,%9}, {%0,%1,%2,%3};"
                 : "+f"(c[0]), "+f"(c[1]), "+f"(c[2]), "+f"(c[3])
                 : "r"(a[0]), "r"(a[1]), "r"(a[2]), "r"(a[3]), "r"(b0), "r"(b1));
}

// smem: single A plane [8 warps][32 rows][112B]
// 112B = 28 words stride: 8-row ldmatrix groups hit banks {0,28,24,20,16,12,8,4}
// -> conflict-free. Cols 0..95 (3 ktiles) fit.
constexpr int ROWB = 112;
constexpr int WARP_PLANE = 32 * ROWB;        // 3584
constexpr int SMEM_TOTAL = 8 * WARP_PLANE;   // 28672

__device__ __forceinline__ uint32_t a_addr(uint32_t base, int mt, int kt, int lane) {
    const int g = lane >> 3;
    const int row = mt * 16 + (lane & 7) + ((g & 1) << 3);
    const int col = ((g >> 1) << 4) + kt * 32;
    return base + row * ROWB + col;
}

// ---------------------------------------------------------------------------
// KSEL: 0 = R1 (edge_msg), 1 = R2 (edge_out)
template<int KSEL>
__device__ __forceinline__ void edge_mlp_tensor(
    char* sm, uint32_t smu, int tid,
    const int* __restrict__ ei, float* __restrict__ out, int E) {
    const int wid  = tid >> 5;
    const int lane = tid & 31;
    const uint32_t pB = smu + wid * WARP_PLANE;
    char* pC = sm + wid * WARP_PLANE;
    const int eb = blockIdx.x * 256 + wid * 32;
    constexpr int B1 = (KSEL == 0) ? R1B1 : R2B1;
    constexpr int B2 = (KSEL == 0) ? R1B2 : R2B2;
    const int c0base = (lane & 3) * 2;
    const uint2* __restrict__ gF = g_bfrag + KSEL * FRAG_CNT;

    __syncwarp();   // order stage_inputs stores before ldmatrix cross-lane reads

    // ---- layer 1: 2 composite ktiles ([hi10|lo10|hi10] x [Wh;Wh;Wl]) ----
    {
        uint32_t a0[2][4], a1[2][4];
#pragma unroll
        for (int mt = 0; mt < 2; ++mt) {
            ldsm4(a0[mt], a_addr(pB, mt, 0, lane));
            ldsm4(a1[mt], a_addr(pB, mt, 1, lane));
        }
        float acc[2][5][4];
#pragma unroll
        for (int nt = 0; nt < 5; ++nt) {
            const int c0 = nt * 8 + c0base;
            const float b0 = cP[B1 + c0], b1v = cP[B1 + c0 + 1];
            const uint2 F0 = __ldg(&gF[(0 * 5 + nt) * 32 + lane]);
            const uint2 F1 = __ldg(&gF[(1 * 5 + nt) * 32 + lane]);
#pragma unroll
            for (int mt = 0; mt < 2; ++mt) {
                acc[mt][nt][0] = b0; acc[mt][nt][1] = b1v;
                acc[mt][nt][2] = b0; acc[mt][nt][3] = b1v;
                mma16816(acc[mt][nt], a0[mt], F0.x, F0.y);
                mma16816(acc[mt][nt], a1[mt], F1.x, F1.y);
            }
        }
        // epilogue: relu + plain fp16 pack -> h1 cols 0..39 (bytes 0..79)
#pragma unroll
        for (int mt = 0; mt < 2; ++mt) {
            const int rA = mt * 16 + (lane >> 2);
            char* r0 = pC + rA * ROWB;
            char* r8 = pC + (rA + 8) * ROWB;
#pragma unroll
            for (int nt = 0; nt < 5; ++nt) {
                const int c0 = nt * 8 + c0base;
                *(uint32_t*)(r0 + 2 * c0) =
                    h2pack(fmaxf(acc[mt][nt][0], 0.f), fmaxf(acc[mt][nt][1], 0.f));
                *(uint32_t*)(r8 + 2 * c0) =
                    h2pack(fmaxf(acc[mt][nt][2], 0.f), fmaxf(acc[mt][nt][3], 0.f));
            }
        }
    }
    __syncwarp();

    // ---- layer 2: pure fp16, K=48 (3 ktiles; cols 40..95 zero) ----
    float acc2[2][5][4];
#pragma unroll
    for (int nt = 0; nt < 5; ++nt) {
        const int c0 = nt * 8 + c0base;
        const float b0 = cP[B2 + c0], b1v = cP[B2 + c0 + 1];
#pragma unroll
        for (int mt = 0; mt < 2; ++mt) {
            acc2[mt][nt][0] = b0; acc2[mt][nt][1] = b1v;
            acc2[mt][nt][2] = b0; acc2[mt][nt][3] = b1v;
        }
    }
#pragma unroll
    for (int kt = 0; kt < 3; ++kt) {
        uint32_t aA[4], aB[4];
        ldsm4(aA, a_addr(pB, 0, kt, lane));
        ldsm4(aB, a_addr(pB, 1, kt, lane));
#pragma unroll
        for (int nt = 0; nt < 5; ++nt) {
            const uint2 F = __ldg(&gF[((2 + kt) * 5 + nt) * 32 + lane]);
            mma16816(acc2[0][nt], aA, F.x, F.y);
            mma16816(acc2[1][nt], aB, F.x, F.y);
        }
    }

    // ---- layer 3 + writeback ----
#pragma unroll
    for (int mt = 0; mt < 2; ++mt) {
        if (KSEL == 0) {
            float p[8] = {0.f, 0.f, 0.f, 0.f, 0.f, 0.f, 0.f, 0.f};
#pragma unroll
            for (int nt = 0; nt < 5; ++nt) {
                const int c0 = nt * 8 + c0base;
                const float v0 = fmaxf(acc2[mt][nt][0], 0.f);
                const float v1 = fmaxf(acc2[mt][nt][1], 0.f);
                const float v2 = fmaxf(acc2[mt][nt][2], 0.f);
                const float v3 = fmaxf(acc2[mt][nt][3], 0.f);
#pragma unroll
                for (int j = 0; j < 4; ++j) {
                    const float w0 = cP[R1W3T + c0 * 4 + j];
                    const float w1 = cP[R1W3T + (c0 + 1) * 4 + j];
                    p[j]     += v0 * w0 + v1 * w1;
                    p[4 + j] += v2 * w0 + v3 * w1;
                }
            }
#pragma unroll
            for (int i = 0; i < 8; ++i) {
                p[i] += __shfl_xor_sync(0xffffffffu, p[i], 1);
                p[i] += __shfl_xor_sync(0xffffffffu, p[i], 2);
            }
            if ((lane & 3) == 0) {
                const int rA = mt * 16 + (lane >> 2);
                const int e1 = eb + rA, e2 = eb + rA + 8;
                if (e1 < E) {
                    const float o0 = p[0] + cP[R1B3 + 0], o1 = p[1] + cP[R1B3 + 1];
                    const float o2 = p[2] + cP[R1B3 + 2], o3 = p[3] + cP[R1B3 + 3];
                    const int d = ei[E + e1];
                    g_emsg[e1] = make_float4(o0, o1, o2, o3);
                    atomicAdd(&g_aggr[d * 4 + 0], o0);
                    atomicAdd(&g_aggr[d * 4 + 1], o1);
                    atomicAdd(&g_aggr[d * 4 + 2], o2);
                    atomicAdd(&g_aggr[d * 4 + 3], o3);
                }
                if (e2 < E) {
                    const float o0 = p[4] + cP[R1B3 + 0], o1 = p[5] + cP[R1B3 + 1];
                    const float o2 = p[6] + cP[R1B3 + 2], o3 = p[7] + cP[R1B3 + 3];
                    const int d = ei[E + e2];
                    g_emsg[e2] = make_float4(o0, o1, o2, o3);
                    atomicAdd(&g_aggr[d * 4 + 0], o0);
                    atomicAdd(&g_aggr[d * 4 + 1], o1);
                    atomicAdd(&g_aggr[d * 4 + 2], o2);
                    atomicAdd(&g_aggr[d * 4 + 3], o3);
                }
            }
        } else {
            float p0 = 0.f, p1 = 0.f;
#pragma unroll
            for (int nt = 0; nt < 5; ++nt) {
                const int c0 = nt * 8 + c0base;
                const float v0 = fmaxf(acc2[mt][nt][0], 0.f);
                const float v1 = fmaxf(acc2[mt][nt][1], 0.f);
                const float v2 = fmaxf(acc2[mt][nt][2], 0.f);
                const float v3 = fmaxf(acc2[mt][nt][3], 0.f);
                const float w0 = cP[R2W3 + c0], w1 = cP[R2W3 + c0 + 1];
                p0 += v0 * w0 + v1 * w1;
                p1 += v2 * w0 + v3 * w1;
            }
            p0 += __shfl_xor_sync(0xffffffffu, p0, 1);
            p0 += __shfl_xor_sync(0xffffffffu, p0, 2);
            p1 += __shfl_xor_sync(0xffffffffu, p1, 1);
            p1 += __shfl_xor_sync(0xffffffffu, p1, 2);
            if ((lane & 3) == 0) {
                const int rA = mt * 16 + (lane >> 2);
                const int e1 = eb + rA, e2 = eb + rA + 8;
                if (e1 < E) out[e1] = 1.f / (1.f + expf(-(p0 + cP[R2B3])));
                if (e2 < E) out[e2] = 1.f / (1.f + expf(-(p1 + cP[R2B3])));
            }
        }
    }
}

// Stage inputs [hi10|lo10|hi10] (bytes 0-59); zero bytes 60-95 (ktile tails +
// layer-2 K padding region, which the layer-1 epilogue does not overwrite).
__device__ __forceinline__ void stage_inputs(char* sm, int tid, const float* in,
                                             bool valid) {
    const int wid  = tid >> 5;
    const int lane = tid & 31;
    char* r = sm + wid * WARP_PLANE + lane * ROWB;
    if (valid) {
#pragma unroll
        for (int j = 0; j < 5; ++j) {
            uint32_t h, l;
            split2h(in[2 * j], in[2 * j + 1], h, l);
            *(uint32_t*)(r + 4 * j)      = h;
            *(uint32_t*)(r + 20 + 4 * j) = l;
            *(uint32_t*)(r + 40 + 4 * j) = h;
        }
    } else {
#pragma unroll
        for (int j = 0; j < 15; ++j) *(uint32_t*)(r + 4 * j) = 0u;
    }
#pragma unroll
    for (int j = 15; j < 24; ++j) *(uint32_t*)(r + 4 * j) = 0u;   // bytes 60-95
}

// ---------------------------------------------------------------------------
__global__ __launch_bounds__(256, 4)
void edge_msg_kernel(const int* __restrict__ ei,
                     const float* __restrict__ eattr, int E) {
    extern __shared__ char sm[];
    const uint32_t smu = smem_to_u32(sm);
    const int tid = threadIdx.x;
    const int e = blockIdx.x * 256 + tid;

    float in[10];
    if (e < E) {
        const int src = ei[e];
        const int dst = ei[E + e];
        const float4 xd = g_x4[dst];
        const float4 xs = g_x4[src];
        in[0] = xd.x; in[1] = xd.y; in[2] = xd.z;
        in[3] = xs.x; in[4] = xs.y; in[5] = xs.z;
        const float4 ea = reinterpret_cast<const float4*>(eattr)[e];
        in[6] = ea.x; in[7] = ea.y; in[8] = ea.z; in[9] = ea.w;
    }
    stage_inputs(sm, tid, in, e < E);
    edge_mlp_tensor<0>(sm, smu, tid, ei, nullptr, E);
}

__global__ __launch_bounds__(256, 4)
void edge_out_kernel(const int* __restrict__ ei,
                     float* __restrict__ out, int E) {
    extern __shared__ char sm[];
    const uint32_t smu = smem_to_u32(sm);
    const int tid = threadIdx.x;
    const int e = blockIdx.x * 256 + tid;

    float in[10];
    if (e < E) {
        const int src = ei[e];
        const int dst = ei[E + e];
        const float4 xd = g_xt4[dst];
        const float4 xs = g_xt4[src];
        in[0] = xd.x; in[1] = xd.y; in[2] = xd.z;
        in[3] = xs.x; in[4] = xs.y; in[5] = xs.z;
        const float4 em = g_emsg[e];
        in[6] = em.x; in[7] = em.y; in[8] = em.z; in[9] = em.w;
    }
    stage_inputs(sm, tid, in, e < E);
    edge_mlp_tensor<1>(sm, smu, tid, ei, out, E);
}

// ---------------------------------------------------------------------------
// Scalar node MLP (constant bank + FFMA2)
__device__ __forceinline__ void ffma2(unsigned long long& d, unsigned long long a,
                                      unsigned long long b) {
    asm("fma.rn.f32x2 %0, %1, %2, %0;" : "+l"(d) : "l"(a), "l"(b));
}
__device__ __forceinline__ unsigned long long dup2(float a) {
    unsigned long long r;
    asm("mov.b64 %0, {%1, %1};" : "=l"(r) : "f"(a));
    return r;
}
template<int IN, int OUT, int WOFF, int BOFF>
__device__ __forceinline__ void denseC(const float* in, float* out) {
    unsigned long long acc[OUT / 2];
#pragma unroll
    for (int j2 = 0; j2 < OUT / 2; ++j2)
        acc[j2] = *reinterpret_cast<const unsigned long long*>(cP + BOFF + 2 * j2);
#pragma unroll
    for (int k = 0; k < IN; ++k) {
        const unsigned long long a2 = dup2(in[k]);
#pragma unroll
        for (int j2 = 0; j2 < OUT / 2; ++j2)
            ffma2(acc[j2], a2,
                  *reinterpret_cast<const unsigned long long*>(cP + WOFF + k * OUT + 2 * j2));
    }
#pragma unroll
    for (int j2 = 0; j2 < OUT / 2; ++j2) {
        float lo, hi;
        asm("mov.b64 {%0, %1}, %2;" : "=f"(lo), "=f"(hi) : "l"(acc[j2]));
        out[2 * j2] = lo; out[2 * j2 + 1] = hi;
    }
}
template<int N>
__device__ __forceinline__ void relu_(float* v) {
#pragma unroll
    for (int i = 0; i < N; ++i) v[i] = fmaxf(v[i], 0.f);
}

__global__ __launch_bounds__(256)
void node_kernel(int N) {
    const int n = blockIdx.x * 256 + threadIdx.x;
    if (n >= N) return;
    float in[7];
    const float4 xn = g_x4[n];
    in[0] = xn.x; in[1] = xn.y; in[2] = xn.z;
    const float4 ag = reinterpret_cast<const float4*>(g_aggr)[n];
    in[3] = ag.x; in[4] = ag.y; in[5] = ag.z; in[6] = ag.w;
    float h1[40]; denseC<7, 40, OW1T, OB1>(in, h1); relu_<40>(h1);
    float h2[40]; denseC<40, 40, OW2T, OB2>(h1, h2); relu_<40>(h2);
    float o[4];   denseC<40, 4,  OW3T, OB3>(h2, o);
    g_xt4[n] = make_float4(o[0], o[1], o[2], 0.f);
}

// ---------------------------------------------------------------------------
// Prep: constants + composite B fragments + zero g_aggr + padded g_x4.
__device__ __forceinline__ float f16hi(float v) {
    return __half2float(__float2half_rn(v));
}

__global__ void prep_params_kernel(
    const float* __restrict__ x,
    const float* __restrict__ r1w1, const float* __restrict__ r1b1,
    const float* __restrict__ r1w2, const float* __restrict__ r1b2,
    const float* __restrict__ r1w3, const float* __restrict__ r1b3,
    const float* __restrict__ ow1,  const float* __restrict__ ob1,
    const float* __restrict__ ow2,  const float* __restrict__ ob2,
    const float* __restrict__ ow3,  const float* __restrict__ ob3,
    const float* __restrict__ r2w1, const float* __restrict__ r2b1,
    const float* __restrict__ r2w2, const float* __restrict__ r2b2,
    const float* __restrict__ r2w3, const float* __restrict__ r2b3,
    int Nnodes) {
    const int t = blockIdx.x * blockDim.x + threadIdx.x;
    const int S = gridDim.x * blockDim.x;

    for (int i = t; i < Nnodes * 4; i += S) g_aggr[i] = 0.f;
    for (int i = t; i < Nnodes; i += S)
        g_x4[i] = make_float4(x[3 * i], x[3 * i + 1], x[3 * i + 2], 0.f);

    for (int i = t; i < 400;  i += S) { int j = i / 10, k = i % 10; g_cparams[R1W1T + k * 40 + j] = r1w1[i]; }
    for (int i = t; i < 1600; i += S) { int j = i / 40, k = i % 40; g_cparams[R1W2T + k * 40 + j] = r1w2[i]; }
    for (int i = t; i < 160;  i += S) { int j = i / 40, k = i % 40; g_cparams[R1W3T + k * 4 + j]  = r1w3[i]; }
    for (int i = t; i < 280;  i += S) { int j = i / 7,  k = i % 7;  g_cparams[OW1T  + k * 40 + j] = ow1[i];  }
    for (int i = t; i < 1600; i += S) { int j = i / 40, k = i % 40; g_cparams[OW2T  + k * 40 + j] = ow2[i];  }
    for (int i = t; i < 160;  i += S) { int k = i / 4,  j = i % 4;  g_cparams[OW3T + i] = (j < 3) ? ow3[j * 40 + k] : 0.f; }
    for (int i = t; i < 400;  i += S) { int j = i / 10, k = i % 10; g_cparams[R2W1T + k * 40 + j] = r2w1[i]; }
    for (int i = t; i < 1600; i += S) { int j = i / 40, k = i % 40; g_cparams[R2W2T + k * 40 + j] = r2w2[i]; }
    for (int i = t; i < 40;   i += S) {
        g_cparams[R2W3 + i] = r2w3[i];
        g_cparams[R1B1 + i] = r1b1[i]; g_cparams[R1B2 + i] = r1b2[i];
        g_cparams[OB1  + i] = ob1[i];  g_cparams[OB2  + i] = ob2[i];
        g_cparams[R2B1 + i] = r2b1[i]; g_cparams[R2B2 + i] = r2b2[i];
    }
    for (int i = t; i < 4; i += S) {
        g_cparams[R1B3 + i] = r1b3[i];
        g_cparams[OB3  + i] = (i < 3) ? ob3[i] : 0.f;
    }
    if (t == 0) { g_cparams[R2B3] = r2b3[0]; g_cparams[R2B3 + 1] = 0.f; }

    // Composite B fragment tables.
    for (int idx = t; idx < 2 * FRAG_CNT; idx += S) {
        const int ker  = idx / FRAG_CNT;
        const int rem  = idx % FRAG_CNT;
        const int f    = rem / 160;
        const int nt   = (rem % 160) / 32;
        const int lane = rem % 32;
        const float* W1 = ker ? r2w1 : r1w1;
        const float* W2 = ker ? r2w2 : r1w2;
        const int n  = nt * 8 + (lane >> 2);
        const int kb = (lane & 3) * 2;
        const int ksl[4] = {kb, kb + 1, kb + 8, kb + 9};
        float v[4];
#pragma unroll
        for (int i = 0; i < 4; ++i) {
            float val = 0.f;
            if (f < 2) {                         // layer1: [Wh;Wh;Wl]
                const int kc = f * 16 + ksl[i];
                if (kc < 10)      { const float w = W1[n * 10 + kc];      val = f16hi(w); }
                else if (kc < 20) { const float w = W1[n * 10 + kc - 10]; val = f16hi(w); }
                else if (kc < 30) { const float w = W1[n * 10 + kc - 20]; val = w - f16hi(w); }
            } else if (f < 5) {                  // layer2: Wh over K=48 (kc>=40 zero)
                const int kc = (f - 2) * 16 + ksl[i];
                if (kc < 40)      { const float w = W2[n * 40 + kc];      val = f16hi(w); }
            }                                    // f 5-9: zero (unused)
            v[i] = val;
        }
        uint2 F;
        F.x = h2pack(v[0], v[1]);
        F.y = h2pack(v[2], v[3]);
        g_bfrag[idx] = F;
    }
}

// ---------------------------------------------------------------------------
extern "C" void kernel_launch(void* const* d_in, const int* in_sizes, int n_in,
                              void* d_out, int out_size) {
    const float* x     = (const float*)d_in[0];
    const int*   ei    = (const int*)d_in[1];
    const float* eattr = (const float*)d_in[2];
    const float *r1w1 = (const float*)d_in[3],  *r1b1 = (const float*)d_in[4];
    const float *r1w2 = (const float*)d_in[5],  *r1b2 = (const float*)d_in[6];
    const float *r1w3 = (const float*)d_in[7],  *r1b3 = (const float*)d_in[8];
    const float *ow1  = (const float*)d_in[9],  *ob1  = (const float*)d_in[10];
    const float *ow2  = (const float*)d_in[11], *ob2  = (const float*)d_in[12];
    const float *ow3  = (const float*)d_in[13], *ob3  = (const float*)d_in[14];
    const float *r2w1 = (const float*)d_in[15], *r2b1 = (const float*)d_in[16];
    const float *r2w2 = (const float*)d_in[17], *r2b2 = (const float*)d_in[18];
    const float *r2w3 = (const float*)d_in[19], *r2b3 = (const float*)d_in[20];

    const int N = in_sizes[0] / 3;
    const int E = in_sizes[2] / 4;

    cudaFuncSetAttribute(edge_msg_kernel,
                         cudaFuncAttributeMaxDynamicSharedMemorySize, SMEM_TOTAL);
    cudaFuncSetAttribute(edge_out_kernel,
                         cudaFuncAttributeMaxDynamicSharedMemorySize, SMEM_TOTAL);

    prep_params_kernel<<<1600, 256>>>(x,
                                      r1w1, r1b1, r1w2, r1b2, r1w3, r1b3,
                                      ow1, ob1, ow2, ob2, ow3, ob3,
                                      r2w1, r2b1, r2w2, r2b2, r2w3, r2b3, N);
    void* src = nullptr;
    cudaGetSymbolAddress(&src, g_cparams);
    cudaMemcpyToSymbolAsync(cP, src, CP_TOTAL * sizeof(float), 0,
                            cudaMemcpyDeviceToDevice, 0);

    const int eblk = (E + 255) / 256;
    edge_msg_kernel<<<eblk, 256, SMEM_TOTAL>>>(ei, eattr, E);
    node_kernel<<<(N + 255) / 256, 256>>>(N);
    edge_out_kernel<<<eblk, 256, SMEM_TOTAL>>>(ei, (float*)d_out, E);
}